// round 10
// baseline (speedup 1.0000x reference)
#include <cuda_runtime.h>
#include <cuda_bf16.h>

// EdgeGCN: 2x GCNConv (sym-norm, self loops) + edge MLP + folded scoring head.
// out[e] = sA[src] + sB[dst] + relu(ea@eW1+eb1) . v + c
//   v = eW2 @ fW[128:192],  c = eb2 . fW[128:192] + fb
// Layer-2 fully folded (linear):
//   uA = W2 @ fW[0:64], uB = W2 @ fW[64:128]
//   tA[n] = dis[n]*(h[n].uA), tB[n] = dis[n]*(h[n].uB)
//   sA[n] = dis[n]*(sum_{src->n} tA[src] + tA[n]) + b2.fW[0:64]   (sB analogous)
// Layer-1: m = (x@W1)*dis ; h = relu(dis*(sum+self)+b1)
// Aggregation via fixed-capacity buckets (no histogram/scan, no float atomics).

#define NMAX 100000
#define EMAX 1600000
#define HID 64
#define CAP 128   // bucket capacity per node (Poisson(16) in-degree; 128 is >> max)

__device__ float  g_m[(size_t)NMAX * HID];
__device__ float  g_h[(size_t)NMAX * HID];
__device__ float  g_dis[NMAX];
__device__ float  g_sA[NMAX];
__device__ float  g_sB[NMAX];
__device__ float2 g_tab[NMAX];
__device__ int    g_cnt[NMAX];
__device__ int    g_srcs[(size_t)NMAX * CAP];
__device__ float  g_v[HID];
__device__ float  g_uA[HID];
__device__ float  g_uB[HID];
__device__ float  g_c;
__device__ float  g_cA;
__device__ float  g_cB;

typedef unsigned long long ull;

__device__ __forceinline__ ull pack2(float x) {
    ull r; asm("mov.b64 %0, {%1, %1};" : "=l"(r) : "f"(x)); return r;
}
__device__ __forceinline__ ull fma2(ull a, ull b, ull c) {
    ull d; asm("fma.rn.f32x2 %0, %1, %2, %3;" : "=l"(d) : "l"(a), "l"(b), "l"(c)); return d;
}
__device__ __forceinline__ void unpack2(ull v, float& lo, float& hi) {
    asm("mov.b64 {%0, %1}, %2;" : "=f"(lo), "=f"(hi) : "l"(v));
}

// ---------------- bucket build ----------------

__global__ void k_zero(int N) {
    int i = blockIdx.x * blockDim.x + threadIdx.x;
    if (i < N) g_cnt[i] = 0;
}

__global__ void k_fill(const int* __restrict__ src, const int* __restrict__ dst, int E) {
    int e = blockIdx.x * blockDim.x + threadIdx.x;
    if (e >= E) return;
    int d = dst[e];
    int pos = atomicAdd(&g_cnt[d], 1);
    if (pos < CAP) g_srcs[(size_t)d * CAP + pos] = src[e];
}

__global__ void k_dis(int N) {
    int n = blockIdx.x * blockDim.x + threadIdx.x;
    if (n < N) g_dis[n] = rsqrtf((float)g_cnt[n] + 1.0f);
}

// ---------------- prep: warp per output scalar -----------------------------
__global__ __launch_bounds__(256) void k_prep(const float* __restrict__ eW2,
                                              const float* __restrict__ eb2,
                                              const float* __restrict__ W2,
                                              const float* __restrict__ b2,
                                              const float* __restrict__ fW,
                                              const float* __restrict__ fb) {
    int gid = blockIdx.x * blockDim.x + threadIdx.x;
    int w = gid >> 5;
    int l = gid & 31;
    float acc = 0.0f;
    if (w < 64) {
        acc = eW2[w * HID + l] * fW[128 + l] + eW2[w * HID + l + 32] * fW[160 + l];
    } else if (w < 128) {
        int k = w - 64;
        acc = W2[k * HID + l] * fW[l] + W2[k * HID + l + 32] * fW[l + 32];
    } else if (w < 192) {
        int k = w - 128;
        acc = W2[k * HID + l] * fW[64 + l] + W2[k * HID + l + 32] * fW[96 + l];
    } else if (w == 192) {
        acc = eb2[l] * fW[128 + l] + eb2[l + 32] * fW[160 + l];
    } else if (w == 193) {
        acc = b2[l] * fW[l] + b2[l + 32] * fW[l + 32];
    } else if (w == 194) {
        acc = b2[l] * fW[64 + l] + b2[l + 32] * fW[96 + l];
    } else return;
    #pragma unroll
    for (int o = 16; o; o >>= 1) acc += __shfl_down_sync(0xFFFFFFFFu, acc, o);
    if (l == 0) {
        if (w < 64) g_v[w] = acc;
        else if (w < 128) g_uA[w - 64] = acc;
        else if (w < 192) g_uB[w - 128] = acc;
        else if (w == 192) g_c = acc + fb[0];
        else if (w == 193) g_cA = acc;
        else g_cB = acc;
    }
}

// ---------------- GEMM1: g_m = (x[N,128] @ W1[128,64]) * dis --------------
// 64x64 tile, 256 threads, each 4 rows x 4 cols; f32x2 over column pairs.
__global__ __launch_bounds__(256) void k_gemm1(const float* __restrict__ x,
                                               const float* __restrict__ W, int N) {
    __shared__ __align__(16) float Wsh[64 * 64];
    __shared__ __align__(16) float xsh[64 * 65];
    int tid = threadIdx.x;
    int rg = tid >> 4;
    int cg = tid & 15;
    int base = blockIdx.x * 64;

    // accumulators: 4 rows x 2 column-pairs (cols cg*4 .. cg*4+3)
    ull a0p = 0, a0q = 0, a1p = 0, a1q = 0;
    ull a2p = 0, a2q = 0, a3p = 0, a3q = 0;

    const float4* x4 = (const float4*)x;
    const float4* W4 = (const float4*)W;

    for (int kt = 0; kt < 2; kt++) {
        __syncthreads();
        #pragma unroll
        for (int i = 0; i < 4; i++) {
            int idx = tid + i * 256;
            int kk = idx >> 4;
            int cq = idx & 15;
            *(float4*)&Wsh[kk * 64 + cq * 4] = W4[(size_t)(kt * 64 + kk) * 16 + cq];
        }
        #pragma unroll
        for (int i = 0; i < 4; i++) {
            int idx = tid + i * 256;
            int row = idx >> 4;
            int kq = idx & 15;
            int n = base + row;
            float4 v = make_float4(0.f, 0.f, 0.f, 0.f);
            if (n < N) v = x4[(size_t)n * 32 + kt * 16 + kq];
            float* p = &xsh[row * 65 + kq * 4];
            p[0] = v.x; p[1] = v.y; p[2] = v.z; p[3] = v.w;
        }
        __syncthreads();

        #pragma unroll 16
        for (int k = 0; k < 64; k++) {
            ulonglong2 w = *(const ulonglong2*)&Wsh[k * 64 + cg * 4]; // cols {0,1},{2,3}
            ull x0 = pack2(xsh[(rg * 4 + 0) * 65 + k]);
            ull x1 = pack2(xsh[(rg * 4 + 1) * 65 + k]);
            ull x2 = pack2(xsh[(rg * 4 + 2) * 65 + k]);
            ull x3 = pack2(xsh[(rg * 4 + 3) * 65 + k]);
            a0p = fma2(x0, w.x, a0p); a0q = fma2(x0, w.y, a0q);
            a1p = fma2(x1, w.x, a1p); a1q = fma2(x1, w.y, a1q);
            a2p = fma2(x2, w.x, a2p); a2q = fma2(x2, w.y, a2q);
            a3p = fma2(x3, w.x, a3p); a3q = fma2(x3, w.y, a3q);
        }
    }

    int n0 = base + rg * 4;
    float lo, hi;
    if (n0 + 0 < N) { float d = g_dis[n0 + 0]; float4 o;
        unpack2(a0p, lo, hi); o.x = lo * d; o.y = hi * d;
        unpack2(a0q, lo, hi); o.z = lo * d; o.w = hi * d;
        *(float4*)&g_m[(size_t)(n0 + 0) * 64 + cg * 4] = o; }
    if (n0 + 1 < N) { float d = g_dis[n0 + 1]; float4 o;
        unpack2(a1p, lo, hi); o.x = lo * d; o.y = hi * d;
        unpack2(a1q, lo, hi); o.z = lo * d; o.w = hi * d;
        *(float4*)&g_m[(size_t)(n0 + 1) * 64 + cg * 4] = o; }
    if (n0 + 2 < N) { float d = g_dis[n0 + 2]; float4 o;
        unpack2(a2p, lo, hi); o.x = lo * d; o.y = hi * d;
        unpack2(a2q, lo, hi); o.z = lo * d; o.w = hi * d;
        *(float4*)&g_m[(size_t)(n0 + 2) * 64 + cg * 4] = o; }
    if (n0 + 3 < N) { float d = g_dis[n0 + 3]; float4 o;
        unpack2(a3p, lo, hi); o.x = lo * d; o.y = hi * d;
        unpack2(a3q, lo, hi); o.z = lo * d; o.w = hi * d;
        *(float4*)&g_m[(size_t)(n0 + 3) * 64 + cg * 4] = o; }
}

// ---------------- gather layer 1: 4x unrolled (MLP=4) ----------------------
__global__ void k_gather1(const float* __restrict__ b1, int N) {
    int tid = threadIdx.x;
    int j = tid & 63;
    int n = blockIdx.x * 4 + (tid >> 6);
    if (n >= N) return;
    int cnt = g_cnt[n];
    const int* sp = &g_srcs[(size_t)n * CAP];
    float acc = 0.0f;
    int i = 0;
    for (; i + 4 <= cnt; i += 4) {
        int s0 = sp[i + 0];
        int s1 = sp[i + 1];
        int s2 = sp[i + 2];
        int s3 = sp[i + 3];
        float v0 = g_m[(size_t)s0 * 64 + j];
        float v1 = g_m[(size_t)s1 * 64 + j];
        float v2 = g_m[(size_t)s2 * 64 + j];
        float v3 = g_m[(size_t)s3 * 64 + j];
        acc += (v0 + v1) + (v2 + v3);
    }
    for (; i < cnt; i++)
        acc += g_m[(size_t)sp[i] * 64 + j];
    float v = g_dis[n] * (acc + g_m[(size_t)n * 64 + j]) + b1[j];
    g_h[(size_t)n * 64 + j] = fmaxf(v, 0.0f);
}

// ---------------- tab: tA = dis*(h.uA), tB = dis*(h.uB); warp per node ----
__global__ void k_tab(int N) {
    int gid = blockIdx.x * blockDim.x + threadIdx.x;
    int warp = gid >> 5;
    int lane = gid & 31;
    if (warp >= N) return;
    float h0 = g_h[(size_t)warp * 64 + lane];
    float h1 = g_h[(size_t)warp * 64 + lane + 32];
    float a = h0 * g_uA[lane] + h1 * g_uA[lane + 32];
    float b = h0 * g_uB[lane] + h1 * g_uB[lane + 32];
    #pragma unroll
    for (int o = 16; o; o >>= 1) {
        a += __shfl_down_sync(0xFFFFFFFFu, a, o);
        b += __shfl_down_sync(0xFFFFFFFFu, b, o);
    }
    if (lane == 0) {
        float dis = g_dis[warp];
        g_tab[warp] = make_float2(a * dis, b * dis);
    }
}

// ---------------- scalar gather 2: 4x unrolled; thread per node -----------
__global__ void k_gather2s(int N) {
    int n = blockIdx.x * blockDim.x + threadIdx.x;
    if (n >= N) return;
    int cnt = g_cnt[n];
    const int* sp = &g_srcs[(size_t)n * CAP];
    float2 self = g_tab[n];
    float a = self.x, b = self.y;
    int i = 0;
    for (; i + 4 <= cnt; i += 4) {
        float2 t0 = g_tab[sp[i + 0]];
        float2 t1 = g_tab[sp[i + 1]];
        float2 t2 = g_tab[sp[i + 2]];
        float2 t3 = g_tab[sp[i + 3]];
        a += (t0.x + t1.x) + (t2.x + t3.x);
        b += (t0.y + t1.y) + (t2.y + t3.y);
    }
    for (; i < cnt; i++) {
        float2 t = g_tab[sp[i]];
        a += t.x; b += t.y;
    }
    float dis = g_dis[n];
    g_sA[n] = dis * a + g_cA;
    g_sB[n] = dis * b + g_cB;
}

// ---------------- edge kernel: 2 edges/thread, f32x2 packed FMAs ----------
__global__ __launch_bounds__(256) void k_edge(const float* __restrict__ ea_g,
                                              const int* __restrict__ src,
                                              const int* __restrict__ dst,
                                              const float* __restrict__ eW1,
                                              const float* __restrict__ eb1,
                                              float* __restrict__ out, int E) {
    __shared__ __align__(16) float shW[16 * 64];
    __shared__ __align__(16) float shB[64];
    __shared__ __align__(16) float shV[64];
    int tid = threadIdx.x;
    *(float4*)&shW[tid * 4] = ((const float4*)eW1)[tid];
    if (tid < 64) { shB[tid] = eb1[tid]; shV[tid] = g_v[tid]; }
    __syncthreads();

    int e0 = blockIdx.x * 512 + tid;
    int e1 = e0 + 256;
    bool ok0 = e0 < E;
    bool ok1 = e1 < E;

    ull a0p[16];
    ull a1p[16];
    const float4* p0 = (const float4*)(ea_g + (size_t)e0 * 16);
    const float4* p1 = (const float4*)(ea_g + (size_t)e1 * 16);
    #pragma unroll
    for (int i = 0; i < 4; i++) {
        float4 t = ok0 ? p0[i] : make_float4(0.f, 0.f, 0.f, 0.f);
        a0p[i * 4 + 0] = pack2(t.x); a0p[i * 4 + 1] = pack2(t.y);
        a0p[i * 4 + 2] = pack2(t.z); a0p[i * 4 + 3] = pack2(t.w);
    }
    #pragma unroll
    for (int i = 0; i < 4; i++) {
        float4 t = ok1 ? p1[i] : make_float4(0.f, 0.f, 0.f, 0.f);
        a1p[i * 4 + 0] = pack2(t.x); a1p[i * 4 + 1] = pack2(t.y);
        a1p[i * 4 + 2] = pack2(t.z); a1p[i * 4 + 3] = pack2(t.w);
    }

    float score0 = 0.0f;
    float score1 = 0.0f;

    #pragma unroll 2
    for (int cb = 0; cb < 8; cb++) {
        ulonglong2 b01 = *(const ulonglong2*)&shB[cb * 8];
        ulonglong2 b23 = *(const ulonglong2*)&shB[cb * 8 + 4];
        ull accA0 = b01.x, accA1 = b01.y, accA2 = b23.x, accA3 = b23.y;
        ull accB0 = b01.x, accB1 = b01.y, accB2 = b23.x, accB3 = b23.y;
        #pragma unroll
        for (int k = 0; k < 16; k++) {
            ulonglong2 w01 = *(const ulonglong2*)&shW[k * 64 + cb * 8];
            ulonglong2 w23 = *(const ulonglong2*)&shW[k * 64 + cb * 8 + 4];
            accA0 = fma2(a0p[k], w01.x, accA0);
            accA1 = fma2(a0p[k], w01.y, accA1);
            accA2 = fma2(a0p[k], w23.x, accA2);
            accA3 = fma2(a0p[k], w23.y, accA3);
            accB0 = fma2(a1p[k], w01.x, accB0);
            accB1 = fma2(a1p[k], w01.y, accB1);
            accB2 = fma2(a1p[k], w23.x, accB2);
            accB3 = fma2(a1p[k], w23.y, accB3);
        }
        float4 v0 = *(const float4*)&shV[cb * 8];
        float4 v1 = *(const float4*)&shV[cb * 8 + 4];
        float lo, hi;
        unpack2(accA0, lo, hi); score0 += fmaxf(lo, 0.f) * v0.x + fmaxf(hi, 0.f) * v0.y;
        unpack2(accA1, lo, hi); score0 += fmaxf(lo, 0.f) * v0.z + fmaxf(hi, 0.f) * v0.w;
        unpack2(accA2, lo, hi); score0 += fmaxf(lo, 0.f) * v1.x + fmaxf(hi, 0.f) * v1.y;
        unpack2(accA3, lo, hi); score0 += fmaxf(lo, 0.f) * v1.z + fmaxf(hi, 0.f) * v1.w;
        unpack2(accB0, lo, hi); score1 += fmaxf(lo, 0.f) * v0.x + fmaxf(hi, 0.f) * v0.y;
        unpack2(accB1, lo, hi); score1 += fmaxf(lo, 0.f) * v0.z + fmaxf(hi, 0.f) * v0.w;
        unpack2(accB2, lo, hi); score1 += fmaxf(lo, 0.f) * v1.x + fmaxf(hi, 0.f) * v1.y;
        unpack2(accB3, lo, hi); score1 += fmaxf(lo, 0.f) * v1.z + fmaxf(hi, 0.f) * v1.w;
    }

    float c0 = g_c;
    if (ok0) out[e0] = score0 + c0 + g_sA[src[e0]] + g_sB[dst[e0]];
    if (ok1) out[e1] = score1 + c0 + g_sA[src[e1]] + g_sB[dst[e1]];
}

// ---------------- launch ----------------

extern "C" void kernel_launch(void* const* d_in, const int* in_sizes, int n_in,
                              void* d_out, int out_size) {
    const float* x        = (const float*)d_in[0];
    const int* ei         = (const int*)d_in[1];     // int32 (JAX canonicalizes int64)
    const float* ea       = (const float*)d_in[2];
    const float* W1       = (const float*)d_in[3];
    const float* b1       = (const float*)d_in[4];
    const float* W2       = (const float*)d_in[5];
    const float* b2       = (const float*)d_in[6];
    const float* eW1      = (const float*)d_in[7];
    const float* eb1      = (const float*)d_in[8];
    const float* eW2      = (const float*)d_in[9];
    const float* eb2      = (const float*)d_in[10];
    const float* fW       = (const float*)d_in[11];
    const float* fb       = (const float*)d_in[12];
    float* out            = (float*)d_out;

    int N = in_sizes[0] / 128;
    int E = in_sizes[2] / 16;
    const int* src = ei;
    const int* dst = ei + E;

    // bucket build
    k_zero<<<(N + 255) / 256, 256>>>(N);
    k_fill<<<(E + 255) / 256, 256>>>(src, dst, E);
    k_dis<<<(N + 255) / 256, 256>>>(N);
    k_prep<<<25, 256>>>(eW2, eb2, W2, b2, fW, fb);

    // layer 1
    k_gemm1<<<(N + 63) / 64, 256>>>(x, W1, N);
    k_gather1<<<(N + 3) / 4, 256>>>(b1, N);

    // layer 2 (folded): per-node scalars + scalar gather
    k_tab<<<((long long)N * 32 + 255) / 256, 256>>>(N);
    k_gather2s<<<(N + 255) / 256, 256>>>(N);

    // edge MLP + score
    k_edge<<<(E + 511) / 512, 256>>>(ea, src, dst, eW1, eb1, out, E);
}

// round 11
// speedup vs baseline: 1.0332x; 1.0332x over previous
#include <cuda_runtime.h>
#include <cuda_bf16.h>

// EdgeGCN: 2x GCNConv (sym-norm, self loops) + edge MLP + folded scoring head.
// out[e] = sA[src] + sB[dst] + relu(ea@eW1+eb1) . v + c
//   v = eW2 @ fW[128:192],  c = eb2 . fW[128:192] + fb
// Layer-2 fully folded (linear):
//   uA = W2 @ fW[0:64], uB = W2 @ fW[64:128]
//   tab[n] = dis[n]*(h[n].uA, h[n].uB)   (computed inside gather1; g_h never stored)
//   sA[n] = dis[n]*(sum_{src->n} tA[src] + tA[n]) + b2.fW[0:64]   (sB analogous)
// Layer-1: m = (x@W1)*dis ; h = relu(dis*(sum+self)+b1)
// Aggregation via fixed-capacity buckets (no histogram/scan, no float atomics).

#define NMAX 100000
#define EMAX 1600000
#define HID 64
#define CAP 128   // bucket capacity per node (Poisson(16) in-degree; 128 is >> max)

__device__ float  g_m[(size_t)NMAX * HID];
__device__ float  g_sA[NMAX];
__device__ float  g_sB[NMAX];
__device__ float2 g_tab[NMAX];
__device__ int    g_cnt[NMAX];
__device__ int    g_srcs[(size_t)NMAX * CAP];
__device__ float  g_v[HID];
__device__ float  g_uA[HID];
__device__ float  g_uB[HID];
__device__ float  g_c;
__device__ float  g_cA;
__device__ float  g_cB;

typedef unsigned long long ull;

__device__ __forceinline__ ull pack2(float x) {
    ull r; asm("mov.b64 %0, {%1, %1};" : "=l"(r) : "f"(x)); return r;
}
__device__ __forceinline__ ull pack2f(float lo, float hi) {
    ull r; asm("mov.b64 %0, {%1, %2};" : "=l"(r) : "f"(lo), "f"(hi)); return r;
}
__device__ __forceinline__ ull fma2(ull a, ull b, ull c) {
    ull d; asm("fma.rn.f32x2 %0, %1, %2, %3;" : "=l"(d) : "l"(a), "l"(b), "l"(c)); return d;
}
__device__ __forceinline__ void unpack2(ull v, float& lo, float& hi) {
    asm("mov.b64 {%0, %1}, %2;" : "=f"(lo), "=f"(hi) : "l"(v));
}

// ---------------- bucket build ----------------

__global__ void k_zero(int N) {
    int i = blockIdx.x * blockDim.x + threadIdx.x;
    if (i < N) g_cnt[i] = 0;
}

__global__ void k_fill(const int* __restrict__ src, const int* __restrict__ dst, int E) {
    int e = blockIdx.x * blockDim.x + threadIdx.x;
    if (e >= E) return;
    int d = dst[e];
    int pos = atomicAdd(&g_cnt[d], 1);
    if (pos < CAP) g_srcs[(size_t)d * CAP + pos] = src[e];
}

// ---------------- prep: warp per output scalar -----------------------------
__global__ __launch_bounds__(256) void k_prep(const float* __restrict__ eW2,
                                              const float* __restrict__ eb2,
                                              const float* __restrict__ W2,
                                              const float* __restrict__ b2,
                                              const float* __restrict__ fW,
                                              const float* __restrict__ fb) {
    int gid = blockIdx.x * blockDim.x + threadIdx.x;
    int w = gid >> 5;
    int l = gid & 31;
    float acc = 0.0f;
    if (w < 64) {
        acc = eW2[w * HID + l] * fW[128 + l] + eW2[w * HID + l + 32] * fW[160 + l];
    } else if (w < 128) {
        int k = w - 64;
        acc = W2[k * HID + l] * fW[l] + W2[k * HID + l + 32] * fW[l + 32];
    } else if (w < 192) {
        int k = w - 128;
        acc = W2[k * HID + l] * fW[64 + l] + W2[k * HID + l + 32] * fW[96 + l];
    } else if (w == 192) {
        acc = eb2[l] * fW[128 + l] + eb2[l + 32] * fW[160 + l];
    } else if (w == 193) {
        acc = b2[l] * fW[l] + b2[l + 32] * fW[l + 32];
    } else if (w == 194) {
        acc = b2[l] * fW[64 + l] + b2[l + 32] * fW[96 + l];
    } else return;
    #pragma unroll
    for (int o = 16; o; o >>= 1) acc += __shfl_down_sync(0xFFFFFFFFu, acc, o);
    if (l == 0) {
        if (w < 64) g_v[w] = acc;
        else if (w < 128) g_uA[w - 64] = acc;
        else if (w < 192) g_uB[w - 128] = acc;
        else if (w == 192) g_c = acc + fb[0];
        else if (w == 193) g_cA = acc;
        else g_cB = acc;
    }
}

// ---------------- GEMM1: g_m = (x[N,128] @ W1[128,64]) * dis --------------
// 64x64 tile, 256 threads, each 4 rows x 4 cols; f32x2 over column pairs.
__global__ __launch_bounds__(256) void k_gemm1(const float* __restrict__ x,
                                               const float* __restrict__ W, int N) {
    __shared__ __align__(16) float Wsh[64 * 64];
    __shared__ __align__(16) float xsh[64 * 65];
    int tid = threadIdx.x;
    int rg = tid >> 4;
    int cg = tid & 15;
    int base = blockIdx.x * 64;

    ull a0p = 0, a0q = 0, a1p = 0, a1q = 0;
    ull a2p = 0, a2q = 0, a3p = 0, a3q = 0;

    const float4* x4 = (const float4*)x;
    const float4* W4 = (const float4*)W;

    for (int kt = 0; kt < 2; kt++) {
        __syncthreads();
        #pragma unroll
        for (int i = 0; i < 4; i++) {
            int idx = tid + i * 256;
            int kk = idx >> 4;
            int cq = idx & 15;
            *(float4*)&Wsh[kk * 64 + cq * 4] = W4[(size_t)(kt * 64 + kk) * 16 + cq];
        }
        #pragma unroll
        for (int i = 0; i < 4; i++) {
            int idx = tid + i * 256;
            int row = idx >> 4;
            int kq = idx & 15;
            int n = base + row;
            float4 v = make_float4(0.f, 0.f, 0.f, 0.f);
            if (n < N) v = x4[(size_t)n * 32 + kt * 16 + kq];
            float* p = &xsh[row * 65 + kq * 4];
            p[0] = v.x; p[1] = v.y; p[2] = v.z; p[3] = v.w;
        }
        __syncthreads();

        #pragma unroll 16
        for (int k = 0; k < 64; k++) {
            ulonglong2 w = *(const ulonglong2*)&Wsh[k * 64 + cg * 4];
            ull x0 = pack2(xsh[(rg * 4 + 0) * 65 + k]);
            ull x1 = pack2(xsh[(rg * 4 + 1) * 65 + k]);
            ull x2 = pack2(xsh[(rg * 4 + 2) * 65 + k]);
            ull x3 = pack2(xsh[(rg * 4 + 3) * 65 + k]);
            a0p = fma2(x0, w.x, a0p); a0q = fma2(x0, w.y, a0q);
            a1p = fma2(x1, w.x, a1p); a1q = fma2(x1, w.y, a1q);
            a2p = fma2(x2, w.x, a2p); a2q = fma2(x2, w.y, a2q);
            a3p = fma2(x3, w.x, a3p); a3q = fma2(x3, w.y, a3q);
        }
    }

    int n0 = base + rg * 4;
    float lo, hi;
    if (n0 + 0 < N) { float d = rsqrtf((float)g_cnt[n0 + 0] + 1.0f); float4 o;
        unpack2(a0p, lo, hi); o.x = lo * d; o.y = hi * d;
        unpack2(a0q, lo, hi); o.z = lo * d; o.w = hi * d;
        *(float4*)&g_m[(size_t)(n0 + 0) * 64 + cg * 4] = o; }
    if (n0 + 1 < N) { float d = rsqrtf((float)g_cnt[n0 + 1] + 1.0f); float4 o;
        unpack2(a1p, lo, hi); o.x = lo * d; o.y = hi * d;
        unpack2(a1q, lo, hi); o.z = lo * d; o.w = hi * d;
        *(float4*)&g_m[(size_t)(n0 + 1) * 64 + cg * 4] = o; }
    if (n0 + 2 < N) { float d = rsqrtf((float)g_cnt[n0 + 2] + 1.0f); float4 o;
        unpack2(a2p, lo, hi); o.x = lo * d; o.y = hi * d;
        unpack2(a2q, lo, hi); o.z = lo * d; o.w = hi * d;
        *(float4*)&g_m[(size_t)(n0 + 2) * 64 + cg * 4] = o; }
    if (n0 + 3 < N) { float d = rsqrtf((float)g_cnt[n0 + 3] + 1.0f); float4 o;
        unpack2(a3p, lo, hi); o.x = lo * d; o.y = hi * d;
        unpack2(a3q, lo, hi); o.z = lo * d; o.w = hi * d;
        *(float4*)&g_m[(size_t)(n0 + 3) * 64 + cg * 4] = o; }
}

// ---------------- gather1 + tab fused: h computed in-register --------------
// 4 nodes/block, 64 threads/node (2 warps). tab[n] = dis*(h.uA, h.uB).
__global__ __launch_bounds__(256) void k_gather1tab(const float* __restrict__ b1, int N) {
    __shared__ float red[8][2];
    int tid = threadIdx.x;
    int j = tid & 63;
    int local = tid >> 6;
    int warp = tid >> 5;
    int lane = tid & 31;
    int n = blockIdx.x * 4 + local;
    float pa = 0.0f, pb = 0.0f;
    float dis = 0.0f;
    if (n < N) {
        int cnt = g_cnt[n];
        const int* sp = &g_srcs[(size_t)n * CAP];
        float acc = 0.0f;
        int i = 0;
        for (; i + 4 <= cnt; i += 4) {
            int s0 = sp[i + 0];
            int s1 = sp[i + 1];
            int s2 = sp[i + 2];
            int s3 = sp[i + 3];
            float v0 = g_m[(size_t)s0 * 64 + j];
            float v1 = g_m[(size_t)s1 * 64 + j];
            float v2 = g_m[(size_t)s2 * 64 + j];
            float v3 = g_m[(size_t)s3 * 64 + j];
            acc += (v0 + v1) + (v2 + v3);
        }
        for (; i < cnt; i++)
            acc += g_m[(size_t)sp[i] * 64 + j];
        dis = rsqrtf((float)cnt + 1.0f);
        float h = fmaxf(dis * (acc + g_m[(size_t)n * 64 + j]) + b1[j], 0.0f);
        pa = h * g_uA[j];
        pb = h * g_uB[j];
    }
    #pragma unroll
    for (int o = 16; o; o >>= 1) {
        pa += __shfl_down_sync(0xFFFFFFFFu, pa, o);
        pb += __shfl_down_sync(0xFFFFFFFFu, pb, o);
    }
    if (lane == 0) { red[warp][0] = pa; red[warp][1] = pb; }
    __syncthreads();
    if ((tid & 63) == 0 && n < N) {
        float a = red[local * 2][0] + red[local * 2 + 1][0];
        float b = red[local * 2][1] + red[local * 2 + 1][1];
        g_tab[n] = make_float2(a * dis, b * dis);
    }
}

// ---------------- scalar gather 2: 4x unrolled; thread per node -----------
__global__ void k_gather2s(int N) {
    int n = blockIdx.x * blockDim.x + threadIdx.x;
    if (n >= N) return;
    int cnt = g_cnt[n];
    const int* sp = &g_srcs[(size_t)n * CAP];
    float2 self = g_tab[n];
    float a = self.x, b = self.y;
    int i = 0;
    for (; i + 4 <= cnt; i += 4) {
        float2 t0 = g_tab[sp[i + 0]];
        float2 t1 = g_tab[sp[i + 1]];
        float2 t2 = g_tab[sp[i + 2]];
        float2 t3 = g_tab[sp[i + 3]];
        a += (t0.x + t1.x) + (t2.x + t3.x);
        b += (t0.y + t1.y) + (t2.y + t3.y);
    }
    for (; i < cnt; i++) {
        float2 t = g_tab[sp[i]];
        a += t.x; b += t.y;
    }
    float dis = rsqrtf((float)cnt + 1.0f);
    g_sA[n] = dis * a + g_cA;
    g_sB[n] = dis * b + g_cB;
}

// ---------------- edge kernel: 4 edges/thread, k-paired f32x2 --------------
// Weights pre-paired in shared as [kk][col]: {W[2kk][col], W[2kk+1][col]}.
// acc lanes hold even/odd-k partial dots; final = lo + hi.
__global__ __launch_bounds__(256, 2) void k_edge(const float* __restrict__ ea_g,
                                                 const int* __restrict__ src,
                                                 const int* __restrict__ dst,
                                                 const float* __restrict__ eW1,
                                                 const float* __restrict__ eb1,
                                                 float* __restrict__ out, int E) {
    __shared__ __align__(16) ull shW2[8 * 64];   // [kk][col]
    __shared__ __align__(16) float shB[64];
    __shared__ __align__(16) float shV[64];
    int tid = threadIdx.x;
    #pragma unroll
    for (int i = 0; i < 2; i++) {
        int id = tid + i * 256;
        int kk = id >> 6;
        int col = id & 63;
        shW2[id] = pack2f(eW1[(2 * kk) * 64 + col], eW1[(2 * kk + 1) * 64 + col]);
    }
    if (tid < 64) { shB[tid] = eb1[tid]; shV[tid] = g_v[tid]; }
    __syncthreads();

    int e0 = blockIdx.x * 1024 + tid;
    ull fe0[8], fe1[8], fe2[8], fe3[8];
    bool ok0 = e0 < E, ok1 = e0 + 256 < E, ok2 = e0 + 512 < E, ok3 = e0 + 768 < E;
    {
        const float4* p0 = (const float4*)(ea_g + (size_t)e0 * 16);
        const float4* p1 = (const float4*)(ea_g + (size_t)(e0 + 256) * 16);
        const float4* p2 = (const float4*)(ea_g + (size_t)(e0 + 512) * 16);
        const float4* p3 = (const float4*)(ea_g + (size_t)(e0 + 768) * 16);
        #pragma unroll
        for (int i = 0; i < 4; i++) {
            float4 t0 = ok0 ? p0[i] : make_float4(0.f, 0.f, 0.f, 0.f);
            float4 t1 = ok1 ? p1[i] : make_float4(0.f, 0.f, 0.f, 0.f);
            float4 t2 = ok2 ? p2[i] : make_float4(0.f, 0.f, 0.f, 0.f);
            float4 t3 = ok3 ? p3[i] : make_float4(0.f, 0.f, 0.f, 0.f);
            fe0[2 * i] = pack2f(t0.x, t0.y); fe0[2 * i + 1] = pack2f(t0.z, t0.w);
            fe1[2 * i] = pack2f(t1.x, t1.y); fe1[2 * i + 1] = pack2f(t1.z, t1.w);
            fe2[2 * i] = pack2f(t2.x, t2.y); fe2[2 * i + 1] = pack2f(t2.z, t2.w);
            fe3[2 * i] = pack2f(t3.x, t3.y); fe3[2 * i + 1] = pack2f(t3.z, t3.w);
        }
    }

    float sc0 = 0.f, sc1 = 0.f, sc2 = 0.f, sc3 = 0.f;

    #pragma unroll 1
    for (int cb = 0; cb < 32; cb++) {          // 2 cols per chunk
        int c0 = cb * 2;
        ull a00 = 0, a01 = 0, a10 = 0, a11 = 0;
        ull a20 = 0, a21 = 0, a30 = 0, a31 = 0;
        #pragma unroll
        for (int kk = 0; kk < 8; kk++) {
            ulonglong2 w = *(const ulonglong2*)&shW2[kk * 64 + c0];  // cols c0, c0+1
            a00 = fma2(fe0[kk], w.x, a00); a01 = fma2(fe0[kk], w.y, a01);
            a10 = fma2(fe1[kk], w.x, a10); a11 = fma2(fe1[kk], w.y, a11);
            a20 = fma2(fe2[kk], w.x, a20); a21 = fma2(fe2[kk], w.y, a21);
            a30 = fma2(fe3[kk], w.x, a30); a31 = fma2(fe3[kk], w.y, a31);
        }
        float b0 = shB[c0], b1v = shB[c0 + 1];
        float v0 = shV[c0], v1v = shV[c0 + 1];
        float lo, hi;
        unpack2(a00, lo, hi); sc0 += fmaxf(lo + hi + b0, 0.f) * v0;
        unpack2(a01, lo, hi); sc0 += fmaxf(lo + hi + b1v, 0.f) * v1v;
        unpack2(a10, lo, hi); sc1 += fmaxf(lo + hi + b0, 0.f) * v0;
        unpack2(a11, lo, hi); sc1 += fmaxf(lo + hi + b1v, 0.f) * v1v;
        unpack2(a20, lo, hi); sc2 += fmaxf(lo + hi + b0, 0.f) * v0;
        unpack2(a21, lo, hi); sc2 += fmaxf(lo + hi + b1v, 0.f) * v1v;
        unpack2(a30, lo, hi); sc3 += fmaxf(lo + hi + b0, 0.f) * v0;
        unpack2(a31, lo, hi); sc3 += fmaxf(lo + hi + b1v, 0.f) * v1v;
    }

    float cc = g_c;
    if (ok0) out[e0] = sc0 + cc + g_sA[src[e0]] + g_sB[dst[e0]];
    if (ok1) { int e = e0 + 256; out[e] = sc1 + cc + g_sA[src[e]] + g_sB[dst[e]]; }
    if (ok2) { int e = e0 + 512; out[e] = sc2 + cc + g_sA[src[e]] + g_sB[dst[e]]; }
    if (ok3) { int e = e0 + 768; out[e] = sc3 + cc + g_sA[src[e]] + g_sB[dst[e]]; }
}

// ---------------- launch ----------------

extern "C" void kernel_launch(void* const* d_in, const int* in_sizes, int n_in,
                              void* d_out, int out_size) {
    const float* x        = (const float*)d_in[0];
    const int* ei         = (const int*)d_in[1];     // int32 (JAX canonicalizes int64)
    const float* ea       = (const float*)d_in[2];
    const float* W1       = (const float*)d_in[3];
    const float* b1       = (const float*)d_in[4];
    const float* W2       = (const float*)d_in[5];
    const float* b2       = (const float*)d_in[6];
    const float* eW1      = (const float*)d_in[7];
    const float* eb1      = (const float*)d_in[8];
    const float* eW2      = (const float*)d_in[9];
    const float* eb2      = (const float*)d_in[10];
    const float* fW       = (const float*)d_in[11];
    const float* fb       = (const float*)d_in[12];
    float* out            = (float*)d_out;

    int N = in_sizes[0] / 128;
    int E = in_sizes[2] / 16;
    const int* src = ei;
    const int* dst = ei + E;

    // bucket build
    k_zero<<<(N + 255) / 256, 256>>>(N);
    k_fill<<<(E + 255) / 256, 256>>>(src, dst, E);
    k_prep<<<25, 256>>>(eW2, eb2, W2, b2, fW, fb);

    // layer 1 (+ fused layer-2 dot products)
    k_gemm1<<<(N + 63) / 64, 256>>>(x, W1, N);
    k_gather1tab<<<(N + 3) / 4, 256>>>(b1, N);

    // layer 2 (folded): scalar gather over tab
    k_gather2s<<<(N + 255) / 256, 256>>>(N);

    // edge MLP + score
    k_edge<<<(E + 1023) / 1024, 256>>>(ea, src, dst, eW1, eb1, out, E);
}